// round 12
// baseline (speedup 1.0000x reference)
#include <cuda_runtime.h>
#include <cuda_fp16.h>
#include <cstdint>

// ---------------- problem constants ----------------
#define H_IMG 200
#define W_IMG 176
#define CIN   256
#define PCH   28
#define BATCH 4
#define NBOX  2048
#define HW    (H_IMG*W_IMG)

#define TW    64     // CTA tile width (pixels)
#define TH    4      // CTA tile height
#define CBLK  16     // input channels per k-step
#define NCB   (CIN/CBLK)   // 16

// ---------------- smem layout (bytes, dynamic) ----------------
#define CELL      48
#define XROWS     6
#define XCOLS     66
#define XBYTES    (XROWS*XCOLS*CELL)       // 19008 (fp16 x buffer)
#define BBYTES    (288*CELL)               // 13824 per buffer (w_hi only)
#define SM_XH     0
#define SM_B      (SM_XH + XBYTES)         // 19008 ; 2 buffers
#define SM_W2     (SM_B + 2*BBYTES)        // 46656
#define SM_SHIFT  (SM_W2 + 3136)           // 49792
#define SM_TOTAL  (SM_SHIFT + 128)         // 49920
// D exchange (256 px x 33 f32 = 33792 B) reuses smem after final sync

#define XITEMS (XROWS*XCOLS*8)             // 3168 channel-pairs
#define NXIT   13                          // ceil(3168/256)

// ---------------- device scratch ----------------
__device__ float g_feat2[(size_t)BATCH * PCH * HW];
// weights: [cb16][tap9][n32][k16] fp16 (hi only)
__device__ __align__(16) __half g_wB[NCB * 9 * 32 * CBLK];
__device__ float g_shift[PCH];

// ---------------- helpers ----------------
__device__ __forceinline__ uint32_t smem_u32(const void* p) {
    uint32_t a;
    asm("{ .reg .u64 t; cvta.to.shared.u64 t, %1; cvt.u32.u64 %0, t; }" : "=r"(a) : "l"(p));
    return a;
}
__device__ __forceinline__ void ldmatrix_x4(uint32_t& r0, uint32_t& r1, uint32_t& r2, uint32_t& r3,
                                            uint32_t addr) {
    asm volatile("ldmatrix.sync.aligned.m8n8.x4.shared.b16 {%0,%1,%2,%3}, [%4];"
                 : "=r"(r0), "=r"(r1), "=r"(r2), "=r"(r3) : "r"(addr));
}
__device__ __forceinline__ void mma_fp16(float& d0, float& d1, float& d2, float& d3,
                                         uint32_t a0, uint32_t a1, uint32_t a2, uint32_t a3,
                                         uint32_t b0, uint32_t b1) {
    asm volatile(
        "mma.sync.aligned.m16n8k16.row.col.f32.f16.f16.f32 "
        "{%0,%1,%2,%3}, {%4,%5,%6,%7}, {%8,%9}, {%0,%1,%2,%3};"
        : "+f"(d0), "+f"(d1), "+f"(d2), "+f"(d3)
        : "r"(a0), "r"(a1), "r"(a2), "r"(a3), "r"(b0), "r"(b1));
}
__device__ __forceinline__ void cp_async16(uint32_t dst, const void* src) {
    asm volatile("cp.async.ca.shared.global [%0], [%1], 16;" :: "r"(dst), "l"(src));
}
#define CP_COMMIT() asm volatile("cp.async.commit_group;" ::: "memory")
#define CP_WAIT0()  asm volatile("cp.async.wait_group 0;" ::: "memory")

// ---------------- prep: BN fold + fp16 weight layout ----------------
__global__ void prep_kernel(const float* __restrict__ w1,
                            const float* __restrict__ gamma,
                            const float* __restrict__ beta,
                            const float* __restrict__ mean,
                            const float* __restrict__ var) {
    int idx = blockIdx.x * blockDim.x + threadIdx.x;
    if (idx < PCH) {
        float inv = gamma[idx] * rsqrtf(var[idx] + 1e-3f);
        g_shift[idx] = beta[idx] - mean[idx] * inv;
    }
    if (idx < NCB * 9 * 32 * CBLK) {     // 73728
        int k = idx & 15;
        int tmp = idx >> 4;
        int n = tmp & 31; tmp >>= 5;
        int t = tmp % 9;
        int cb = tmp / 9;
        float w = 0.f;
        if (n < PCH) {
            float sc = gamma[n] * rsqrtf(var[n] + 1e-3f);
            w = w1[((size_t)n * CIN + (cb * CBLK + k)) * 9 + t] * sc;
        }
        g_wB[idx] = __float2half_rn(w);
    }
}

// ---------------- fused conv1+BN+ReLU+conv2 (fp16 single-term mma.sync) ----------------
__global__ __launch_bounds__(256, 3)
void conv_kernel(const float* __restrict__ x, const float* __restrict__ w2) {
    extern __shared__ __align__(16) char smem[];
    const int tid  = threadIdx.x;
    const int wid  = tid >> 5;
    const int lane = tid & 31;
    const int x0 = blockIdx.x * TW;
    const int y0 = blockIdx.y * TH;
    const int b  = blockIdx.z;

    const uint32_t s_xh = smem_u32(smem) + SM_XH;
    const uint32_t s_b0 = smem_u32(smem) + SM_B;
    float* w2s = (float*)(smem + SM_W2);
    float* shs = (float*)(smem + SM_SHIFT);
    uint32_t* xh32 = (uint32_t*)(smem + SM_XH);

    for (int k = tid; k < PCH * PCH; k += 256) w2s[k] = w2[k];
    if (tid < PCH) shs[tid] = g_shift[tid];

    // warp tile: row ry = wid&3, 32 px starting at px0 = (wid>>2)*32
    const int ry  = wid & 3;
    const int px0 = (wid >> 2) * 32;
    const int g   = lane >> 2;
    const int c2  = (lane & 3) * 2;

    float d[2][4][4];
#pragma unroll
    for (int m = 0; m < 2; m++)
#pragma unroll
        for (int i = 0; i < 4; i++)
#pragma unroll
            for (int j = 0; j < 4; j++) d[m][i][j] = 0.f;

    const float* xb = x + (size_t)b * CIN * HW;
    const char* wsrc = (const char*)g_wB;

    const int a_pix   = lane & 15;
    const int a_khalf = lane >> 4;
    const int b_n     = ((lane >> 4) << 3) + (lane & 7);
    const int b_khalf = (lane >> 3) & 1;

    // ---- B(0) via cp.async into buffer 0 (576 x 16B chunks) ----
    {
#pragma unroll
        for (int i = 0; i < 3; i++) {
            int u = tid + i * 256;
            if (u < 576)
                cp_async16(s_b0 + (u >> 1) * CELL + (u & 1) * 16, wsrc + u * 16);
        }
        CP_COMMIT();
    }

    // ---- x(0) register prefetch ----
    float xv0[NXIT], xv1[NXIT];
    {
#pragma unroll
        for (int i = 0; i < NXIT; i++) {
            int u = tid + i * 256;
            xv0[i] = 0.f; xv1[i] = 0.f;
            if (u < XITEMS) {
                int ch2 = u / (XROWS * XCOLS);
                int rem = u - ch2 * (XROWS * XCOLS);
                int r = rem / XCOLS;
                int c = rem - r * XCOLS;
                int gy = y0 - 1 + r, gx = x0 - 1 + c;
                if (gy >= 0 && gy < H_IMG && gx >= 0 && gx < W_IMG) {
                    const float* p = xb + (size_t)(2 * ch2) * HW + gy * W_IMG + gx;
                    xv0[i] = p[0];
                    xv1[i] = p[HW];
                }
            }
        }
    }

    for (int cb = 0; cb < NCB; cb++) {
        __syncthreads();     // previous MMA phase done reading smem

        // ---- issue B(cb+1) cp.async into the other buffer ----
        if (cb + 1 < NCB) {
            uint32_t dstb = s_b0 + ((cb + 1) & 1) * BBYTES;
            const char* srcb = wsrc + (size_t)(cb + 1) * 9216;
#pragma unroll
            for (int i = 0; i < 3; i++) {
                int u = tid + i * 256;
                if (u < 576)
                    cp_async16(dstb + (u >> 1) * CELL + (u & 1) * 16, srcb + u * 16);
            }
        }
        CP_COMMIT();

        // ---- convert prefetched x regs -> fp16 smem ----
#pragma unroll
        for (int i = 0; i < NXIT; i++) {
            int u = tid + i * 256;
            if (u < XITEMS) {
                int ch2 = u / (XROWS * XCOLS);
                int rem = u - ch2 * (XROWS * XCOLS);
                int r = rem / XCOLS;
                int c = rem - r * XCOLS;
                uint32_t hp;
                asm("cvt.rn.f16x2.f32 %0, %1, %2;" : "=r"(hp) : "f"(xv1[i]), "f"(xv0[i]));
                xh32[(r * XCOLS + c) * 12 + ch2] = hp;
            }
        }
        CP_WAIT0();          // B landed
        __syncthreads();

        // ---- prefetch x(cb+1) (LDGs fly during MMA phase) ----
        if (cb + 1 < NCB) {
            const float* base = xb + (size_t)(cb + 1) * CBLK * HW;
#pragma unroll
            for (int i = 0; i < NXIT; i++) {
                int u = tid + i * 256;
                xv0[i] = 0.f; xv1[i] = 0.f;
                if (u < XITEMS) {
                    int ch2 = u / (XROWS * XCOLS);
                    int rem = u - ch2 * (XROWS * XCOLS);
                    int r = rem / XCOLS;
                    int c = rem - r * XCOLS;
                    int gy = y0 - 1 + r, gx = x0 - 1 + c;
                    if (gy >= 0 && gy < H_IMG && gx >= 0 && gx < W_IMG) {
                        const float* p = base + (size_t)(2 * ch2) * HW + gy * W_IMG + gx;
                        xv0[i] = p[0];
                        xv1[i] = p[HW];
                    }
                }
            }
        }

        // ---- MMA phase: 9 taps, 2 M-tiles per warp, single term ----
        const uint32_t s_b = s_b0 + (cb & 1) * BBYTES;
#pragma unroll
        for (int t = 0; t < 9; t++) {
            const int dy = t / 3, dx = t - 3 * dy;
            uint32_t ah[2][4];
#pragma unroll
            for (int m = 0; m < 2; m++) {
                uint32_t aoff = (uint32_t)(((ry + dy) * XCOLS + px0 + m * 16 + dx + a_pix) * CELL
                                           + a_khalf * 16);
                ldmatrix_x4(ah[m][0], ah[m][1], ah[m][2], ah[m][3], s_xh + aoff);
            }
#pragma unroll
            for (int ntp = 0; ntp < 2; ntp++) {
                uint32_t brow = (uint32_t)((t * 32 + ntp * 16 + b_n) * CELL + b_khalf * 16);
                uint32_t bh0, bh1, bh2, bh3;
                ldmatrix_x4(bh0, bh1, bh2, bh3, s_b + brow);
#pragma unroll
                for (int m = 0; m < 2; m++) {
                    float* d0 = d[m][ntp * 2];
                    float* d1 = d[m][ntp * 2 + 1];
                    mma_fp16(d0[0], d0[1], d0[2], d0[3], ah[m][0], ah[m][1], ah[m][2], ah[m][3], bh0, bh1);
                    mma_fp16(d1[0], d1[1], d1[2], d1[3], ah[m][0], ah[m][1], ah[m][2], ah[m][3], bh2, bh3);
                }
            }
        }
    }

    // ---- exchange D through smem (stride 33 => conflict-free) ----
    __syncthreads();
    float* sD = (float*)(smem + SM_XH);
#pragma unroll
    for (int m = 0; m < 2; m++) {
        const int pixbase = ry * TW + px0 + m * 16;
#pragma unroll
        for (int nt = 0; nt < 4; nt++) {
            int n = nt * 8 + c2;
            sD[(pixbase + g) * 33 + n]         = d[m][nt][0];
            sD[(pixbase + g) * 33 + n + 1]     = d[m][nt][1];
            sD[(pixbase + g + 8) * 33 + n]     = d[m][nt][2];
            sD[(pixbase + g + 8) * 33 + n + 1] = d[m][nt][3];
        }
    }
    __syncthreads();

    // ---- BN shift + ReLU + conv2(1x1) + store: 1 pixel per thread ----
    {
        const int pix = tid;
        float rl[PCH];
#pragma unroll
        for (int q = 0; q < PCH; q++)
            rl[q] = fmaxf(sD[pix * 33 + q] + shs[q], 0.f);

        int px = x0 + (pix & 63);
        int py = y0 + (pix >> 6);
        if (px < W_IMG) {
#pragma unroll 4
            for (int p = 0; p < PCH; p++) {
                float o = 0.f;
#pragma unroll
                for (int q = 0; q < PCH; q++)
                    o = fmaf(w2s[p * PCH + q], rl[q], o);
                g_feat2[((size_t)b * PCH + p) * HW + py * W_IMG + px] = o;
            }
        }
    }
}

// ---------------- rotated position-sensitive sampling: one warp per box ----------------
__global__ void sample_kernel(const float* __restrict__ boxes, float* __restrict__ out) {
    int gwarp = (blockIdx.x * blockDim.x + threadIdx.x) >> 5;
    int lane  = threadIdx.x & 31;
    if (gwarp >= BATCH * NBOX) return;
    int b = gwarp >> 11;
    int n = gwarp & (NBOX - 1);
    const float* bx = boxes + (size_t)(b * NBOX + n) * 7;

    float val = 0.f;
    if (lane < PCH) {
        float xg = bx[0], yg = bx[1], wg = bx[3], lg = bx[4], rg = bx[6];
        int i = lane / 7;
        int j = lane - i * 7;
        float lx = (float)i * (1.f / 3.f) - 0.5f;
        float ly = (float)j * (1.f / 6.f) - 0.5f;
        float xx = lx * wg;
        float yy = ly * lg;
        float sT, cT;
        sincosf(rg, &sT, &cT);
        float gx = (xx * cT + yy * sT + xg) * 2.5f;
        float gy = (yy * cT - xx * sT + yg + 40.f) * 2.5f;

        const float* img = g_feat2 + ((size_t)b * PCH + lane) * HW;
        float xf = floorf(gx), yf = floorf(gy);
        int xi = (int)xf, yi = (int)yf;
        float fx = gx - xf, fy = gy - yf;
        float Ia = 0.f, Ib = 0.f, Ic = 0.f, Id = 0.f;
        bool vx0 = (xi >= 0) && (xi <= W_IMG - 1);
        bool vx1 = (xi + 1 >= 0) && (xi + 1 <= W_IMG - 1);
        bool vy0 = (yi >= 0) && (yi <= H_IMG - 1);
        bool vy1 = (yi + 1 >= 0) && (yi + 1 <= H_IMG - 1);
        if (vy0 && vx0) Ia = img[yi * W_IMG + xi];
        if (vy1 && vx0) Ib = img[(yi + 1) * W_IMG + xi];
        if (vy0 && vx1) Ic = img[yi * W_IMG + xi + 1];
        if (vy1 && vx1) Id = img[(yi + 1) * W_IMG + xi + 1];
        val = (1.f - fx) * (1.f - fy) * Ia + (1.f - fx) * fy * Ib
            + fx * (1.f - fy) * Ic + fx * fy * Id;
    }
#pragma unroll
    for (int off = 16; off; off >>= 1)
        val += __shfl_xor_sync(0xffffffffu, val, off);
    if (lane == 0) out[b * NBOX + n] = val * (1.f / 28.f);
}

// ---------------- launch ----------------
extern "C" void kernel_launch(void* const* d_in, const int* in_sizes, int n_in,
                              void* d_out, int out_size) {
    const float* x     = (const float*)d_in[0];
    const float* boxes = (const float*)d_in[1];
    const float* w1    = (const float*)d_in[2];
    const float* gamma = (const float*)d_in[3];
    const float* beta  = (const float*)d_in[4];
    const float* mean  = (const float*)d_in[5];
    const float* var   = (const float*)d_in[6];
    const float* w2    = (const float*)d_in[7];
    float* out = (float*)d_out;

    cudaFuncSetAttribute(conv_kernel, cudaFuncAttributeMaxDynamicSharedMemorySize, SM_TOTAL);

    prep_kernel<<<576, 256>>>(w1, gamma, beta, mean, var);

    dim3 grid((W_IMG + TW - 1) / TW, H_IMG / TH, BATCH);   // (3, 50, 4) = 600 CTAs
    conv_kernel<<<grid, 256, SM_TOTAL>>>(x, w2);

    sample_kernel<<<(BATCH * NBOX * 32) / 256, 256>>>(boxes, out);
}

// round 13
// speedup vs baseline: 1.7790x; 1.7790x over previous
#include <cuda_runtime.h>
#include <cuda_fp16.h>
#include <cstdint>

// ---------------- problem constants ----------------
#define H_IMG 200
#define W_IMG 176
#define CIN   256
#define PCH   28
#define BATCH 4
#define NBOX  2048
#define HW    (H_IMG*W_IMG)

#define TW    64     // CTA tile width (pixels)
#define TH    4      // CTA tile height
#define CBLK  16     // input channels per k-step
#define NCB   (CIN/CBLK)   // 16

// ---------------- smem layout (bytes, dynamic) ----------------
#define CELL      48
#define XROWS     6
#define XCOLS     66
#define XBYTES    (XROWS*XCOLS*CELL)       // 19008 (fp16 x buffer)
#define BBYTES    (288*CELL)               // 13824 per buffer (w_hi only)
#define SM_XH     0
#define SM_B      (SM_XH + XBYTES)         // 19008 ; 2 buffers
#define SM_W2     (SM_B + 2*BBYTES)        // 46656
#define SM_SHIFT  (SM_W2 + 3136)           // 49792
#define SM_TOTAL  (SM_SHIFT + 128)         // 49920
// D exchange (256 px x 33 f32 = 33792 B) reuses smem after final sync

#define XITEMS (XROWS*XCOLS*8)             // 3168 channel-pairs
#define NXIT   13                          // ceil(3168/256)

// ---------------- device scratch ----------------
__device__ float g_feat2[(size_t)BATCH * PCH * HW];
// weights: [cb16][tap9][n32][k16] fp16 (hi only)
__device__ __align__(16) __half g_wB[NCB * 9 * 32 * CBLK];
__device__ float g_shift[PCH];

// ---------------- helpers ----------------
__device__ __forceinline__ uint32_t smem_u32(const void* p) {
    uint32_t a;
    asm("{ .reg .u64 t; cvta.to.shared.u64 t, %1; cvt.u32.u64 %0, t; }" : "=r"(a) : "l"(p));
    return a;
}
__device__ __forceinline__ void ldmatrix_x4(uint32_t& r0, uint32_t& r1, uint32_t& r2, uint32_t& r3,
                                            uint32_t addr) {
    asm volatile("ldmatrix.sync.aligned.m8n8.x4.shared.b16 {%0,%1,%2,%3}, [%4];"
                 : "=r"(r0), "=r"(r1), "=r"(r2), "=r"(r3) : "r"(addr));
}
__device__ __forceinline__ void mma_fp16(float& d0, float& d1, float& d2, float& d3,
                                         uint32_t a0, uint32_t a1, uint32_t a2, uint32_t a3,
                                         uint32_t b0, uint32_t b1) {
    asm volatile(
        "mma.sync.aligned.m16n8k16.row.col.f32.f16.f16.f32 "
        "{%0,%1,%2,%3}, {%4,%5,%6,%7}, {%8,%9}, {%0,%1,%2,%3};"
        : "+f"(d0), "+f"(d1), "+f"(d2), "+f"(d3)
        : "r"(a0), "r"(a1), "r"(a2), "r"(a3), "r"(b0), "r"(b1));
}
__device__ __forceinline__ void cp_async16(uint32_t dst, const void* src) {
    asm volatile("cp.async.ca.shared.global [%0], [%1], 16;" :: "r"(dst), "l"(src));
}
#define CP_COMMIT() asm volatile("cp.async.commit_group;" ::: "memory")
#define CP_WAIT0()  asm volatile("cp.async.wait_group 0;" ::: "memory")

// ---------------- prep: BN fold + fp16 weight layout ----------------
__global__ void prep_kernel(const float* __restrict__ w1,
                            const float* __restrict__ gamma,
                            const float* __restrict__ beta,
                            const float* __restrict__ mean,
                            const float* __restrict__ var) {
    int idx = blockIdx.x * blockDim.x + threadIdx.x;
    if (idx < PCH) {
        float inv = gamma[idx] * rsqrtf(var[idx] + 1e-3f);
        g_shift[idx] = beta[idx] - mean[idx] * inv;
    }
    if (idx < NCB * 9 * 32 * CBLK) {     // 73728
        int k = idx & 15;
        int tmp = idx >> 4;
        int n = tmp & 31; tmp >>= 5;
        int t = tmp % 9;
        int cb = tmp / 9;
        float w = 0.f;
        if (n < PCH) {
            float sc = gamma[n] * rsqrtf(var[n] + 1e-3f);
            w = w1[((size_t)n * CIN + (cb * CBLK + k)) * 9 + t] * sc;
        }
        g_wB[idx] = __float2half_rn(w);
    }
}

// ---------------- fused conv1+BN+ReLU+conv2 (fp16 single-term mma.sync, occ 2) ----------------
__global__ __launch_bounds__(256, 2)
void conv_kernel(const float* __restrict__ x, const float* __restrict__ w2) {
    extern __shared__ __align__(16) char smem[];
    const int tid  = threadIdx.x;
    const int wid  = tid >> 5;
    const int lane = tid & 31;
    const int x0 = blockIdx.x * TW;
    const int y0 = blockIdx.y * TH;
    const int b  = blockIdx.z;

    const uint32_t s_xh = smem_u32(smem) + SM_XH;
    const uint32_t s_b0 = smem_u32(smem) + SM_B;
    float* w2s = (float*)(smem + SM_W2);
    float* shs = (float*)(smem + SM_SHIFT);
    uint32_t* xh32 = (uint32_t*)(smem + SM_XH);

    for (int k = tid; k < PCH * PCH; k += 256) w2s[k] = w2[k];
    if (tid < PCH) shs[tid] = g_shift[tid];

    // warp tile: row ry = wid&3, 32 px starting at px0 = (wid>>2)*32
    const int ry  = wid & 3;
    const int px0 = (wid >> 2) * 32;
    const int g   = lane >> 2;
    const int c2  = (lane & 3) * 2;

    float d[2][4][4];
#pragma unroll
    for (int m = 0; m < 2; m++)
#pragma unroll
        for (int i = 0; i < 4; i++)
#pragma unroll
            for (int j = 0; j < 4; j++) d[m][i][j] = 0.f;

    const float* xb = x + (size_t)b * CIN * HW;
    const char* wsrc = (const char*)g_wB;

    const int a_pix   = lane & 15;
    const int a_khalf = lane >> 4;
    const int b_n     = ((lane >> 4) << 3) + (lane & 7);
    const int b_khalf = (lane >> 3) & 1;

    // ---- B(0) via cp.async into buffer 0 (576 x 16B chunks) ----
    {
#pragma unroll
        for (int i = 0; i < 3; i++) {
            int u = tid + i * 256;
            if (u < 576)
                cp_async16(s_b0 + (u >> 1) * CELL + (u & 1) * 16, wsrc + u * 16);
        }
        CP_COMMIT();
    }

    // ---- x(0) register prefetch ----
    float xv0[NXIT], xv1[NXIT];
    {
#pragma unroll
        for (int i = 0; i < NXIT; i++) {
            int u = tid + i * 256;
            xv0[i] = 0.f; xv1[i] = 0.f;
            if (u < XITEMS) {
                int ch2 = u / (XROWS * XCOLS);
                int rem = u - ch2 * (XROWS * XCOLS);
                int r = rem / XCOLS;
                int c = rem - r * XCOLS;
                int gy = y0 - 1 + r, gx = x0 - 1 + c;
                if (gy >= 0 && gy < H_IMG && gx >= 0 && gx < W_IMG) {
                    const float* p = xb + (size_t)(2 * ch2) * HW + gy * W_IMG + gx;
                    xv0[i] = p[0];
                    xv1[i] = p[HW];
                }
            }
        }
    }

    for (int cb = 0; cb < NCB; cb++) {
        __syncthreads();     // previous MMA phase done reading smem

        // ---- issue B(cb+1) cp.async into the other buffer ----
        if (cb + 1 < NCB) {
            uint32_t dstb = s_b0 + ((cb + 1) & 1) * BBYTES;
            const char* srcb = wsrc + (size_t)(cb + 1) * 9216;
#pragma unroll
            for (int i = 0; i < 3; i++) {
                int u = tid + i * 256;
                if (u < 576)
                    cp_async16(dstb + (u >> 1) * CELL + (u & 1) * 16, srcb + u * 16);
            }
        }
        CP_COMMIT();

        // ---- convert prefetched x regs -> fp16 smem ----
#pragma unroll
        for (int i = 0; i < NXIT; i++) {
            int u = tid + i * 256;
            if (u < XITEMS) {
                int ch2 = u / (XROWS * XCOLS);
                int rem = u - ch2 * (XROWS * XCOLS);
                int r = rem / XCOLS;
                int c = rem - r * XCOLS;
                uint32_t hp;
                asm("cvt.rn.f16x2.f32 %0, %1, %2;" : "=r"(hp) : "f"(xv1[i]), "f"(xv0[i]));
                xh32[(r * XCOLS + c) * 12 + ch2] = hp;
            }
        }
        CP_WAIT0();          // B landed
        __syncthreads();

        // ---- prefetch x(cb+1) (LDGs fly during MMA phase) ----
        if (cb + 1 < NCB) {
            const float* base = xb + (size_t)(cb + 1) * CBLK * HW;
#pragma unroll
            for (int i = 0; i < NXIT; i++) {
                int u = tid + i * 256;
                xv0[i] = 0.f; xv1[i] = 0.f;
                if (u < XITEMS) {
                    int ch2 = u / (XROWS * XCOLS);
                    int rem = u - ch2 * (XROWS * XCOLS);
                    int r = rem / XCOLS;
                    int c = rem - r * XCOLS;
                    int gy = y0 - 1 + r, gx = x0 - 1 + c;
                    if (gy >= 0 && gy < H_IMG && gx >= 0 && gx < W_IMG) {
                        const float* p = base + (size_t)(2 * ch2) * HW + gy * W_IMG + gx;
                        xv0[i] = p[0];
                        xv1[i] = p[HW];
                    }
                }
            }
        }

        // ---- MMA phase: 9 taps, 2 M-tiles per warp, single term ----
        const uint32_t s_b = s_b0 + (cb & 1) * BBYTES;
#pragma unroll
        for (int t = 0; t < 9; t++) {
            const int dy = t / 3, dx = t - 3 * dy;
            uint32_t ah[2][4];
#pragma unroll
            for (int m = 0; m < 2; m++) {
                uint32_t aoff = (uint32_t)(((ry + dy) * XCOLS + px0 + m * 16 + dx + a_pix) * CELL
                                           + a_khalf * 16);
                ldmatrix_x4(ah[m][0], ah[m][1], ah[m][2], ah[m][3], s_xh + aoff);
            }
#pragma unroll
            for (int ntp = 0; ntp < 2; ntp++) {
                uint32_t brow = (uint32_t)((t * 32 + ntp * 16 + b_n) * CELL + b_khalf * 16);
                uint32_t bh0, bh1, bh2, bh3;
                ldmatrix_x4(bh0, bh1, bh2, bh3, s_b + brow);
#pragma unroll
                for (int m = 0; m < 2; m++) {
                    float* d0 = d[m][ntp * 2];
                    float* d1 = d[m][ntp * 2 + 1];
                    mma_fp16(d0[0], d0[1], d0[2], d0[3], ah[m][0], ah[m][1], ah[m][2], ah[m][3], bh0, bh1);
                    mma_fp16(d1[0], d1[1], d1[2], d1[3], ah[m][0], ah[m][1], ah[m][2], ah[m][3], bh2, bh3);
                }
            }
        }
    }

    // ---- exchange D through smem (stride 33 => conflict-free) ----
    __syncthreads();
    float* sD = (float*)(smem + SM_XH);
#pragma unroll
    for (int m = 0; m < 2; m++) {
        const int pixbase = ry * TW + px0 + m * 16;
#pragma unroll
        for (int nt = 0; nt < 4; nt++) {
            int n = nt * 8 + c2;
            sD[(pixbase + g) * 33 + n]         = d[m][nt][0];
            sD[(pixbase + g) * 33 + n + 1]     = d[m][nt][1];
            sD[(pixbase + g + 8) * 33 + n]     = d[m][nt][2];
            sD[(pixbase + g + 8) * 33 + n + 1] = d[m][nt][3];
        }
    }
    __syncthreads();

    // ---- BN shift + ReLU + conv2(1x1) + store: 1 pixel per thread ----
    {
        const int pix = tid;
        float rl[PCH];
#pragma unroll
        for (int q = 0; q < PCH; q++)
            rl[q] = fmaxf(sD[pix * 33 + q] + shs[q], 0.f);

        int px = x0 + (pix & 63);
        int py = y0 + (pix >> 6);
        if (px < W_IMG) {
#pragma unroll 4
            for (int p = 0; p < PCH; p++) {
                float o = 0.f;
#pragma unroll
                for (int q = 0; q < PCH; q++)
                    o = fmaf(w2s[p * PCH + q], rl[q], o);
                g_feat2[((size_t)b * PCH + p) * HW + py * W_IMG + px] = o;
            }
        }
    }
}

// ---------------- rotated position-sensitive sampling: one warp per box ----------------
__global__ void sample_kernel(const float* __restrict__ boxes, float* __restrict__ out) {
    int gwarp = (blockIdx.x * blockDim.x + threadIdx.x) >> 5;
    int lane  = threadIdx.x & 31;
    if (gwarp >= BATCH * NBOX) return;
    int b = gwarp >> 11;
    int n = gwarp & (NBOX - 1);
    const float* bx = boxes + (size_t)(b * NBOX + n) * 7;

    float val = 0.f;
    if (lane < PCH) {
        float xg = bx[0], yg = bx[1], wg = bx[3], lg = bx[4], rg = bx[6];
        int i = lane / 7;
        int j = lane - i * 7;
        float lx = (float)i * (1.f / 3.f) - 0.5f;
        float ly = (float)j * (1.f / 6.f) - 0.5f;
        float xx = lx * wg;
        float yy = ly * lg;
        float sT, cT;
        sincosf(rg, &sT, &cT);
        float gx = (xx * cT + yy * sT + xg) * 2.5f;
        float gy = (yy * cT - xx * sT + yg + 40.f) * 2.5f;

        const float* img = g_feat2 + ((size_t)b * PCH + lane) * HW;
        float xf = floorf(gx), yf = floorf(gy);
        int xi = (int)xf, yi = (int)yf;
        float fx = gx - xf, fy = gy - yf;
        float Ia = 0.f, Ib = 0.f, Ic = 0.f, Id = 0.f;
        bool vx0 = (xi >= 0) && (xi <= W_IMG - 1);
        bool vx1 = (xi + 1 >= 0) && (xi + 1 <= W_IMG - 1);
        bool vy0 = (yi >= 0) && (yi <= H_IMG - 1);
        bool vy1 = (yi + 1 >= 0) && (yi + 1 <= H_IMG - 1);
        if (vy0 && vx0) Ia = img[yi * W_IMG + xi];
        if (vy1 && vx0) Ib = img[(yi + 1) * W_IMG + xi];
        if (vy0 && vx1) Ic = img[yi * W_IMG + xi + 1];
        if (vy1 && vx1) Id = img[(yi + 1) * W_IMG + xi + 1];
        val = (1.f - fx) * (1.f - fy) * Ia + (1.f - fx) * fy * Ib
            + fx * (1.f - fy) * Ic + fx * fy * Id;
    }
#pragma unroll
    for (int off = 16; off; off >>= 1)
        val += __shfl_xor_sync(0xffffffffu, val, off);
    if (lane == 0) out[b * NBOX + n] = val * (1.f / 28.f);
}

// ---------------- launch ----------------
extern "C" void kernel_launch(void* const* d_in, const int* in_sizes, int n_in,
                              void* d_out, int out_size) {
    const float* x     = (const float*)d_in[0];
    const float* boxes = (const float*)d_in[1];
    const float* w1    = (const float*)d_in[2];
    const float* gamma = (const float*)d_in[3];
    const float* beta  = (const float*)d_in[4];
    const float* mean  = (const float*)d_in[5];
    const float* var   = (const float*)d_in[6];
    const float* w2    = (const float*)d_in[7];
    float* out = (float*)d_out;

    cudaFuncSetAttribute(conv_kernel, cudaFuncAttributeMaxDynamicSharedMemorySize, SM_TOTAL);

    prep_kernel<<<576, 256>>>(w1, gamma, beta, mean, var);

    dim3 grid((W_IMG + TW - 1) / TW, H_IMG / TH, BATCH);   // (3, 50, 4) = 600 CTAs
    conv_kernel<<<grid, 256, SM_TOTAL>>>(x, w2);

    sample_kernel<<<(BATCH * NBOX * 32) / 256, 256>>>(boxes, out);
}

// round 14
// speedup vs baseline: 1.8147x; 1.0200x over previous
#include <cuda_runtime.h>
#include <cuda_fp16.h>
#include <cstdint>

// ---------------- problem constants ----------------
#define H_IMG 200
#define W_IMG 176
#define CIN   256
#define PCH   28
#define BATCH 4
#define NBOX  2048
#define HW    (H_IMG*W_IMG)

#define TW    64     // CTA tile width (pixels)
#define TH    4      // CTA tile height
#define CBLK  16     // input channels per k-step
#define NCB   (CIN/CBLK)   // 16

// ---------------- smem layout (bytes, dynamic) ----------------
#define CELL      48
#define XROWS     6
#define XCOLS     66
#define NCELL     (XROWS*XCOLS)            // 396
#define XBYTES    (NCELL*CELL)             // 19008 per x buffer
#define BBYTES    (288*CELL)               // 13824 per B buffer
#define SM_X      0                        // 2 x buffers
#define SM_B      (SM_X + 2*XBYTES)        // 38016 ; 2 B buffers
#define SM_W2     (SM_B + 2*BBYTES)        // 65664
#define SM_SHIFT  (SM_W2 + 3136)           // 68800
#define SM_TOTAL  (SM_SHIFT + 128)         // 68928
// D exchange (256 px x 33 f32 = 33792 B) reuses smem after final sync

#define XITEMS (NCELL*8)                   // 3168 channel-pairs
#define NXIT   13                          // ceil(3168/256)

// ---------------- device scratch ----------------
__device__ float g_feat2[(size_t)BATCH * PCH * HW];
// weights: [cb16][tap9][n32][k16] fp16
__device__ __align__(16) __half g_wB[NCB * 9 * 32 * CBLK];
__device__ float g_shift[PCH];

// ---------------- helpers ----------------
__device__ __forceinline__ uint32_t smem_u32(const void* p) {
    uint32_t a;
    asm("{ .reg .u64 t; cvta.to.shared.u64 t, %1; cvt.u32.u64 %0, t; }" : "=r"(a) : "l"(p));
    return a;
}
__device__ __forceinline__ void ldmatrix_x4(uint32_t& r0, uint32_t& r1, uint32_t& r2, uint32_t& r3,
                                            uint32_t addr) {
    asm volatile("ldmatrix.sync.aligned.m8n8.x4.shared.b16 {%0,%1,%2,%3}, [%4];"
                 : "=r"(r0), "=r"(r1), "=r"(r2), "=r"(r3) : "r"(addr));
}
__device__ __forceinline__ void mma_fp16(float& d0, float& d1, float& d2, float& d3,
                                         uint32_t a0, uint32_t a1, uint32_t a2, uint32_t a3,
                                         uint32_t b0, uint32_t b1) {
    asm volatile(
        "mma.sync.aligned.m16n8k16.row.col.f32.f16.f16.f32 "
        "{%0,%1,%2,%3}, {%4,%5,%6,%7}, {%8,%9}, {%0,%1,%2,%3};"
        : "+f"(d0), "+f"(d1), "+f"(d2), "+f"(d3)
        : "r"(a0), "r"(a1), "r"(a2), "r"(a3), "r"(b0), "r"(b1));
}
__device__ __forceinline__ void cp_async16(uint32_t dst, const void* src) {
    asm volatile("cp.async.ca.shared.global [%0], [%1], 16;" :: "r"(dst), "l"(src));
}
#define CP_COMMIT() asm volatile("cp.async.commit_group;" ::: "memory")
#define CP_WAIT0()  asm volatile("cp.async.wait_group 0;" ::: "memory")

// ---------------- prep: BN fold + fp16 weight layout ----------------
__global__ void prep_kernel(const float* __restrict__ w1,
                            const float* __restrict__ gamma,
                            const float* __restrict__ beta,
                            const float* __restrict__ mean,
                            const float* __restrict__ var) {
    int idx = blockIdx.x * blockDim.x + threadIdx.x;
    if (idx < PCH) {
        float inv = gamma[idx] * rsqrtf(var[idx] + 1e-3f);
        g_shift[idx] = beta[idx] - mean[idx] * inv;
    }
    if (idx < NCB * 9 * 32 * CBLK) {     // 73728
        int k = idx & 15;
        int tmp = idx >> 4;
        int n = tmp & 31; tmp >>= 5;
        int t = tmp % 9;
        int cb = tmp / 9;
        float w = 0.f;
        if (n < PCH) {
            float sc = gamma[n] * rsqrtf(var[n] + 1e-3f);
            w = w1[((size_t)n * CIN + (cb * CBLK + k)) * 9 + t] * sc;
        }
        g_wB[idx] = __float2half_rn(w);
    }
}

// ---------------- fused conv1+BN+ReLU+conv2 (single-sync pipelined) ----------------
__global__ __launch_bounds__(256, 2)
void conv_kernel(const float* __restrict__ x, const float* __restrict__ w2) {
    extern __shared__ __align__(16) char smem[];
    const int tid  = threadIdx.x;
    const int wid  = tid >> 5;
    const int lane = tid & 31;
    const int x0 = blockIdx.x * TW;
    const int y0 = blockIdx.y * TH;
    const int b  = blockIdx.z;

    const uint32_t s_x0b = smem_u32(smem) + SM_X;
    const uint32_t s_b0  = smem_u32(smem) + SM_B;
    float* w2s = (float*)(smem + SM_W2);
    float* shs = (float*)(smem + SM_SHIFT);

    for (int k = tid; k < PCH * PCH; k += 256) w2s[k] = w2[k];
    if (tid < PCH) shs[tid] = g_shift[tid];

    // warp tile
    const int ry  = wid & 3;
    const int px0 = (wid >> 2) * 32;
    const int g   = lane >> 2;
    const int c2  = (lane & 3) * 2;

    float d[2][4][4];
#pragma unroll
    for (int m = 0; m < 2; m++)
#pragma unroll
        for (int i = 0; i < 4; i++)
#pragma unroll
            for (int j = 0; j < 4; j++) d[m][i][j] = 0.f;

    const float* xb = x + (size_t)b * CIN * HW;
    const char* wsrc = (const char*)g_wB;

    const int a_pix   = lane & 15;
    const int a_khalf = lane >> 4;
    const int b_n     = ((lane >> 4) << 3) + (lane & 7);
    const int b_khalf = (lane >> 3) & 1;

    // ---- hoisted per-thread staging addresses (all div/mod here, once) ----
    int si[NXIT];          // smem u32 word index (or -1)
    int goff[NXIT];        // gmem element offset within channel block
    unsigned vmask = 0;    // bit i: in-image
#pragma unroll
    for (int i = 0; i < NXIT; i++) {
        int u = tid + i * 256;
        si[i] = -1; goff[i] = 0;
        if (u < XITEMS) {
            int ch2 = u / NCELL;
            int rem = u - ch2 * NCELL;
            int r = rem / XCOLS;
            int c = rem - r * XCOLS;
            si[i] = rem * 12 + ch2;
            int gy = y0 - 1 + r, gx = x0 - 1 + c;
            if (gy >= 0 && gy < H_IMG && gx >= 0 && gx < W_IMG) {
                vmask |= (1u << i);
                goff[i] = 2 * ch2 * HW + gy * W_IMG + gx;
            }
        }
    }

    float xv0[NXIT], xv1[NXIT];

    // ---- pre-loop: B(0), x(0) convert, x(1) prefetch ----
    {
#pragma unroll
        for (int i = 0; i < 3; i++) {
            int u = tid + i * 256;
            if (u < 576)
                cp_async16(s_b0 + (u >> 1) * CELL + (u & 1) * 16, wsrc + u * 16);
        }
        CP_COMMIT();
    }
#pragma unroll
    for (int i = 0; i < NXIT; i++) {
        xv0[i] = 0.f; xv1[i] = 0.f;
        if ((vmask >> i) & 1) {
            const float* p = xb + goff[i];
            xv0[i] = p[0];
            xv1[i] = p[HW];
        }
    }
    {
        uint32_t* xbuf = (uint32_t*)(smem + SM_X);
#pragma unroll
        for (int i = 0; i < NXIT; i++) {
            if (si[i] >= 0) {
                uint32_t hp;
                asm("cvt.rn.f16x2.f32 %0, %1, %2;" : "=r"(hp) : "f"(xv1[i]), "f"(xv0[i]));
                xbuf[si[i]] = hp;
            }
        }
    }
#pragma unroll
    for (int i = 0; i < NXIT; i++) {
        xv0[i] = 0.f; xv1[i] = 0.f;
        if ((vmask >> i) & 1) {
            const float* p = xb + CBLK * HW + goff[i];
            xv0[i] = p[0];
            xv1[i] = p[HW];
        }
    }
    CP_WAIT0();
    __syncthreads();

    // ---- main loop: ONE sync per cb ----
    for (int cb = 0; cb < NCB; cb++) {
        // 1. issue B(cb+1)
        if (cb + 1 < NCB) {
            uint32_t dstb = s_b0 + ((cb + 1) & 1) * BBYTES;
            const char* srcb = wsrc + (size_t)(cb + 1) * 9216;
#pragma unroll
            for (int i = 0; i < 3; i++) {
                int u = tid + i * 256;
                if (u < 576)
                    cp_async16(dstb + (u >> 1) * CELL + (u & 1) * 16, srcb + u * 16);
            }
        }
        CP_COMMIT();

        // 2. MMA(cb)
        const uint32_t s_xh = s_x0b + (cb & 1) * XBYTES;
        const uint32_t s_b  = s_b0 + (cb & 1) * BBYTES;
#pragma unroll
        for (int t = 0; t < 9; t++) {
            const int dy = t / 3, dx = t - 3 * dy;
            uint32_t ah[2][4];
#pragma unroll
            for (int m = 0; m < 2; m++) {
                uint32_t aoff = (uint32_t)(((ry + dy) * XCOLS + px0 + m * 16 + dx + a_pix) * CELL
                                           + a_khalf * 16);
                ldmatrix_x4(ah[m][0], ah[m][1], ah[m][2], ah[m][3], s_xh + aoff);
            }
#pragma unroll
            for (int ntp = 0; ntp < 2; ntp++) {
                uint32_t brow = (uint32_t)((t * 32 + ntp * 16 + b_n) * CELL + b_khalf * 16);
                uint32_t bh0, bh1, bh2, bh3;
                ldmatrix_x4(bh0, bh1, bh2, bh3, s_b + brow);
#pragma unroll
                for (int m = 0; m < 2; m++) {
                    float* d0 = d[m][ntp * 2];
                    float* d1 = d[m][ntp * 2 + 1];
                    mma_fp16(d0[0], d0[1], d0[2], d0[3], ah[m][0], ah[m][1], ah[m][2], ah[m][3], bh0, bh1);
                    mma_fp16(d1[0], d1[1], d1[2], d1[3], ah[m][0], ah[m][1], ah[m][2], ah[m][3], bh2, bh3);
                }
            }
        }

        // 3. convert x(cb+1) into the other buffer
        if (cb + 1 < NCB) {
            uint32_t* xbuf = (uint32_t*)(smem + SM_X + ((cb + 1) & 1) * XBYTES);
#pragma unroll
            for (int i = 0; i < NXIT; i++) {
                if (si[i] >= 0) {
                    uint32_t hp;
                    asm("cvt.rn.f16x2.f32 %0, %1, %2;" : "=r"(hp) : "f"(xv1[i]), "f"(xv0[i]));
                    xbuf[si[i]] = hp;
                }
            }
        }

        // 4. prefetch x(cb+2)
        if (cb + 2 < NCB) {
            const float* base = xb + (size_t)(cb + 2) * CBLK * HW;
#pragma unroll
            for (int i = 0; i < NXIT; i++) {
                xv0[i] = 0.f; xv1[i] = 0.f;
                if ((vmask >> i) & 1) {
                    const float* p = base + goff[i];
                    xv0[i] = p[0];
                    xv1[i] = p[HW];
                }
            }
        }

        // 5. B(cb+1) landed + x buffer visible
        CP_WAIT0();
        __syncthreads();
    }

    // ---- exchange D through smem (stride 33 => conflict-free) ----
    float* sD = (float*)(smem + SM_X);
#pragma unroll
    for (int m = 0; m < 2; m++) {
        const int pixbase = ry * TW + px0 + m * 16;
#pragma unroll
        for (int nt = 0; nt < 4; nt++) {
            int n = nt * 8 + c2;
            sD[(pixbase + g) * 33 + n]         = d[m][nt][0];
            sD[(pixbase + g) * 33 + n + 1]     = d[m][nt][1];
            sD[(pixbase + g + 8) * 33 + n]     = d[m][nt][2];
            sD[(pixbase + g + 8) * 33 + n + 1] = d[m][nt][3];
        }
    }
    __syncthreads();

    // ---- BN shift + ReLU + conv2(1x1) + store: 1 pixel per thread ----
    {
        const int pix = tid;
        float rl[PCH];
#pragma unroll
        for (int q = 0; q < PCH; q++)
            rl[q] = fmaxf(sD[pix * 33 + q] + shs[q], 0.f);

        int px = x0 + (pix & 63);
        int py = y0 + (pix >> 6);
        if (px < W_IMG) {
#pragma unroll 4
            for (int p = 0; p < PCH; p++) {
                float o = 0.f;
#pragma unroll
                for (int q = 0; q < PCH; q++)
                    o = fmaf(w2s[p * PCH + q], rl[q], o);
                g_feat2[((size_t)b * PCH + p) * HW + py * W_IMG + px] = o;
            }
        }
    }
}

// ---------------- rotated position-sensitive sampling: one warp per box ----------------
__global__ void sample_kernel(const float* __restrict__ boxes, float* __restrict__ out) {
    int gwarp = (blockIdx.x * blockDim.x + threadIdx.x) >> 5;
    int lane  = threadIdx.x & 31;
    if (gwarp >= BATCH * NBOX) return;
    int b = gwarp >> 11;
    int n = gwarp & (NBOX - 1);
    const float* bx = boxes + (size_t)(b * NBOX + n) * 7;

    float val = 0.f;
    if (lane < PCH) {
        float xg = bx[0], yg = bx[1], wg = bx[3], lg = bx[4], rg = bx[6];
        int i = lane / 7;
        int j = lane - i * 7;
        float lx = (float)i * (1.f / 3.f) - 0.5f;
        float ly = (float)j * (1.f / 6.f) - 0.5f;
        float xx = lx * wg;
        float yy = ly * lg;
        float sT, cT;
        sincosf(rg, &sT, &cT);
        float gx = (xx * cT + yy * sT + xg) * 2.5f;
        float gy = (yy * cT - xx * sT + yg + 40.f) * 2.5f;

        const float* img = g_feat2 + ((size_t)b * PCH + lane) * HW;
        float xf = floorf(gx), yf = floorf(gy);
        int xi = (int)xf, yi = (int)yf;
        float fx = gx - xf, fy = gy - yf;
        float Ia = 0.f, Ib = 0.f, Ic = 0.f, Id = 0.f;
        bool vx0 = (xi >= 0) && (xi <= W_IMG - 1);
        bool vx1 = (xi + 1 >= 0) && (xi + 1 <= W_IMG - 1);
        bool vy0 = (yi >= 0) && (yi <= H_IMG - 1);
        bool vy1 = (yi + 1 >= 0) && (yi + 1 <= H_IMG - 1);
        if (vy0 && vx0) Ia = img[yi * W_IMG + xi];
        if (vy1 && vx0) Ib = img[(yi + 1) * W_IMG + xi];
        if (vy0 && vx1) Ic = img[yi * W_IMG + xi + 1];
        if (vy1 && vx1) Id = img[(yi + 1) * W_IMG + xi + 1];
        val = (1.f - fx) * (1.f - fy) * Ia + (1.f - fx) * fy * Ib
            + fx * (1.f - fy) * Ic + fx * fy * Id;
    }
#pragma unroll
    for (int off = 16; off; off >>= 1)
        val += __shfl_xor_sync(0xffffffffu, val, off);
    if (lane == 0) out[b * NBOX + n] = val * (1.f / 28.f);
}

// ---------------- launch ----------------
extern "C" void kernel_launch(void* const* d_in, const int* in_sizes, int n_in,
                              void* d_out, int out_size) {
    const float* x     = (const float*)d_in[0];
    const float* boxes = (const float*)d_in[1];
    const float* w1    = (const float*)d_in[2];
    const float* gamma = (const float*)d_in[3];
    const float* beta  = (const float*)d_in[4];
    const float* mean  = (const float*)d_in[5];
    const float* var   = (const float*)d_in[6];
    const float* w2    = (const float*)d_in[7];
    float* out = (float*)d_out;

    cudaFuncSetAttribute(conv_kernel, cudaFuncAttributeMaxDynamicSharedMemorySize, SM_TOTAL);

    prep_kernel<<<576, 256>>>(w1, gamma, beta, mean, var);

    dim3 grid((W_IMG + TW - 1) / TW, H_IMG / TH, BATCH);   // (3, 50, 4) = 600 CTAs
    conv_kernel<<<grid, 256, SM_TOTAL>>>(x, w2);

    sample_kernel<<<(BATCH * NBOX * 32) / 256, 256>>>(boxes, out);
}